// round 10
// baseline (speedup 1.0000x reference)
#include <cuda_runtime.h>
#include <cuda_bf16.h>

// SegmentalEmotion: per-sample sliding-window segment means (2-kernel).
// H: [B, T, D] fp32, lengths_sec: [B] fp32.
// Output: S_pad [B, maxS, D] fp32 (+ mask [B, maxS] fp32 appended, auto-detect).
//
// Reference plan (numpy fp64):
//   dur = max(len, 0.001); fps = T/dur
//   win = max(1, rint(fps)); hop = max(1, rint(fps*0.5))
//   n = (T >= win) ? (T-win)/hop + 1 : 0 ; n==0 -> fallback full-T mean
//
// Ledger (R3-R9): workers must read the plan from a pre-built table (__ldg,
// L1-resident after first touch). Any in-worker recompute costs 4-7us; a
// dedicated plan kernel costs a fixed ~5.2us node. This version folds the
// planner into piece_sum block (0,0,0): it computes all 32 integer-exact
// plans, publishes g_plan, threadfence, sets a one-way flag. Other blocks
// spin on a volatile flag load (first execution only; all timed graph
// replays see flag=1 and pay a single broadcast L2 read). Plans are
// recomputed and rewritten identically on every call.
//
// Integer-exact rint(1500/len) (no fp64 for len in [1,1024)):
//   len = m * 2^(e-24)  (frexpf; m 24-bit int, exact)
//   rint decided by  3000*2^(24-e) <=> (2k+/-1)*m  (int64, exact),
//   round-half-to-even on ties; fp32 divide seeds candidate k.

#define T_FRAMES 1500
#define D_DIM    768
#define D_VEC    (D_DIM / 4)   // 192 float4 lanes
#define NTHREADS 192
#define MAX_B    32
#define MAX_NHOP 60            // ceil(1500/25)
#define MAX_NP   4
#define PIECE_TGT 38           // target frames per piece

// piece sums: P[b, j, p, :]
__device__ float g_P[(size_t)MAX_B * MAX_NHOP * MAX_NP * D_DIM];
// plan[b]: {win, hop, n_eff, nhop, np, plen, fallback, pad}
__device__ int g_plan[MAX_B][8];
// one-way latch: 0 until the first planner publication, 1 forever after.
__device__ int g_flag;

struct Plan { int win, hop, n_eff, nhop, np, plen, fallback; };

// rint(num/len) via exact int64 comparisons. lhs = 2*num * 2^(24-e),
// m = 24-bit mantissa of len, k = fp32 candidate (within +-1 of truth).
__device__ __forceinline__ int rint_ratio_exact(long long lhs, long long m, int k)
{
    while (lhs > (2LL * k + 1) * m) ++k;   // x > k+0.5
    while (lhs < (2LL * k - 1) * m) --k;   // x < k-0.5
    if (lhs == (2LL * k + 1) * m) return k + (k & 1);  // tie at k+0.5 -> even
    if (lhs == (2LL * k - 1) * m) return k - (k & 1);  // tie at k-0.5 -> even
    return k;
}

__device__ __forceinline__ Plan compute_plan(float len)
{
    Plan p;
    int win, hop;
    long long n;
    if (len >= 1.0f && len < 1024.0f) {
        int e;
        float mf = frexpf(len, &e);                    // len = mf*2^e
        long long m = (long long)(mf * 16777216.0f);   // mf*2^24, exact
        const int sh = 24 - e;                         // in [14, 23]
        win = rint_ratio_exact(3000LL << sh, m, (int)lrintf(1500.0f / len));
        hop = rint_ratio_exact(1500LL << sh, m, (int)lrintf(750.0f / len));
        if (win < 1) win = 1;
        if (hop < 1) hop = 1;
        n = (T_FRAMES >= win) ? (long long)(T_FRAMES - win) / hop + 1 : 0;
    } else {
        // exact fp64 replica (never taken for len in [5,30); planner-only)
        double dur = fmax((double)len, 0.001);
        double fps = (double)T_FRAMES / dur;
        long long w64 = llrint(fps);       if (w64 < 1) w64 = 1;
        long long h64 = llrint(fps * 0.5); if (h64 < 1) h64 = 1;
        n = ((long long)T_FRAMES >= w64)
                ? ((long long)T_FRAMES - w64) / h64 + 1 : 0;
        if (w64 > T_FRAMES + 1) w64 = T_FRAMES + 1;
        if (h64 > T_FRAMES) h64 = T_FRAMES;
        win = (int)w64;
        hop = (int)h64;
    }
    p.fallback = (n == 0);
    p.win   = win;
    p.hop   = hop;
    p.n_eff = (int)(p.fallback ? 1 : n);
    p.nhop  = (T_FRAMES + hop - 1) / hop;
    int np = (hop + PIECE_TGT - 1) / PIECE_TGT;
    if (np > MAX_NP) np = MAX_NP;
    p.np   = np;
    p.plen = (hop + np - 1) / np;
    return p;
}

// ---------- Phase 1: piece sums (reads H once) + embedded planner ----------
__global__ __launch_bounds__(NTHREADS)
void piece_sum_kernel(const float* __restrict__ H,
                      const float* __restrict__ lens)
{
    const int j   = blockIdx.x;   // hop-chunk index
    const int p   = blockIdx.y;   // piece within chunk
    const int b   = blockIdx.z;
    const int tid = threadIdx.x;

    // Planner: block (0,0,0). Computes all B plans every call; publishes table.
    if (j == 0 && p == 0 && b == 0) {
        if (tid < MAX_B) {
            Plan pl = compute_plan(__ldg(&lens[tid]));
            g_plan[tid][0] = pl.win;
            g_plan[tid][1] = pl.hop;
            g_plan[tid][2] = pl.n_eff;
            g_plan[tid][3] = pl.nhop;
            g_plan[tid][4] = pl.np;
            g_plan[tid][5] = pl.plen;
            g_plan[tid][6] = pl.fallback;
        }
        __syncthreads();
        if (tid == 0) {
            __threadfence();                      // plans visible in L2
            *(volatile int*)&g_flag = 1;          // one-way latch
        }
    }
    // All blocks (incl. planner's non-writer threads): wait for publication.
    // After the first execution the latch is set; this is a single
    // warp-broadcast L2 load per thread on every timed replay.
    while (*(volatile int*)&g_flag == 0) { }

    const int hop  = __ldg(&g_plan[b][1]);
    const int nhop = __ldg(&g_plan[b][3]);
    const int np   = __ldg(&g_plan[b][4]);
    const int plen = __ldg(&g_plan[b][5]);
    if (j >= nhop || p >= np) return;

    int t0 = j * hop + p * plen;
    int chunk_end = j * hop + hop;
    if (chunk_end > T_FRAMES) chunk_end = T_FRAMES;
    int t1 = t0 + plen;
    if (t1 > chunk_end) t1 = chunk_end;

    const float4* __restrict__ Hb =
        (const float4*)H + (size_t)b * T_FRAMES * D_VEC + tid;

    float4 acc = make_float4(0.f, 0.f, 0.f, 0.f);
    int t = t0;
    for (; t + 8 <= t1; t += 8) {
        float4 v0 = __ldcs(&Hb[(t + 0) * D_VEC]);
        float4 v1 = __ldcs(&Hb[(t + 1) * D_VEC]);
        float4 v2 = __ldcs(&Hb[(t + 2) * D_VEC]);
        float4 v3 = __ldcs(&Hb[(t + 3) * D_VEC]);
        float4 v4 = __ldcs(&Hb[(t + 4) * D_VEC]);
        float4 v5 = __ldcs(&Hb[(t + 5) * D_VEC]);
        float4 v6 = __ldcs(&Hb[(t + 6) * D_VEC]);
        float4 v7 = __ldcs(&Hb[(t + 7) * D_VEC]);
        acc.x += v0.x + v1.x + v2.x + v3.x + v4.x + v5.x + v6.x + v7.x;
        acc.y += v0.y + v1.y + v2.y + v3.y + v4.y + v5.y + v6.y + v7.y;
        acc.z += v0.z + v1.z + v2.z + v3.z + v4.z + v5.z + v6.z + v7.z;
        acc.w += v0.w + v1.w + v2.w + v3.w + v4.w + v5.w + v6.w + v7.w;
    }
    for (; t < t1; ++t) {
        float4 v = __ldcs(&Hb[t * D_VEC]);
        acc.x += v.x; acc.y += v.y; acc.z += v.z; acc.w += v.w;
    }

    ((float4*)g_P)[(((size_t)b * MAX_NHOP + j) * MAX_NP + p) * D_VEC + tid] = acc;
}

// ---------- Phase 2: combine piece sums + edge correction (table plan) ----------
__global__ __launch_bounds__(NTHREADS)
void seg_out_kernel(const float* __restrict__ H,
                    float* __restrict__ S,      // [B, maxS, D]
                    float* __restrict__ Mout,   // [B, maxS] or nullptr
                    int maxS)
{
    const int s   = blockIdx.x;
    const int b   = blockIdx.y;
    const int tid = threadIdx.x;

    const int win      = __ldg(&g_plan[b][0]);
    const int hop      = __ldg(&g_plan[b][1]);
    const int n_eff    = __ldg(&g_plan[b][2]);
    const int nhop     = __ldg(&g_plan[b][3]);
    const int np       = __ldg(&g_plan[b][4]);
    const int fallback = __ldg(&g_plan[b][6]);

    float4* outRow = (float4*)(S + ((size_t)b * maxS + s) * D_DIM);

    if (s >= n_eff) {
        outRow[tid] = make_float4(0.f, 0.f, 0.f, 0.f);
        if (Mout != nullptr && tid == 0)
            Mout[(size_t)b * maxS + s] = 0.f;
        return;
    }

    const float4* __restrict__ Pb =
        (const float4*)g_P + (size_t)b * MAX_NHOP * MAX_NP * D_VEC + tid;
    const float4* __restrict__ Hb =
        (const float4*)H + (size_t)b * T_FRAMES * D_VEC + tid;

    float4 acc = make_float4(0.f, 0.f, 0.f, 0.f);
    int cnt;

    if (fallback) {
        for (int jj = 0; jj < nhop; ++jj)
            for (int pp = 0; pp < np; ++pp) {
                float4 v = Pb[((size_t)jj * MAX_NP + pp) * D_VEC];
                acc.x += v.x; acc.y += v.y; acc.z += v.z; acc.w += v.w;
            }
        cnt = T_FRAMES;
    } else {
        const int start = s * hop;
        const int end   = start + win;           // <= T by definition of n
        const bool have2 = (s + 1) < nhop;

        #pragma unroll
        for (int pp = 0; pp < MAX_NP; ++pp) {
            if (pp < np) {
                float4 v = Pb[((size_t)s * MAX_NP + pp) * D_VEC];
                acc.x += v.x; acc.y += v.y; acc.z += v.z; acc.w += v.w;
            }
        }
        if (have2) {
            #pragma unroll
            for (int pp = 0; pp < MAX_NP; ++pp) {
                if (pp < np) {
                    float4 v = Pb[((size_t)(s + 1) * MAX_NP + pp) * D_VEC];
                    acc.x += v.x; acc.y += v.y; acc.z += v.z; acc.w += v.w;
                }
            }
        }
        // chunks s (+ s+1) cover [start, cov_end)
        int cov_end = start + (have2 ? 2 : 1) * hop;
        if (cov_end > T_FRAMES) cov_end = T_FRAMES;

        for (int t = cov_end; t < end; ++t) {     // add missing (<=1)
            float4 v = Hb[t * D_VEC];
            acc.x += v.x; acc.y += v.y; acc.z += v.z; acc.w += v.w;
        }
        for (int t = end; t < cov_end; ++t) {     // subtract excess (<=1)
            float4 v = Hb[t * D_VEC];
            acc.x -= v.x; acc.y -= v.y; acc.z -= v.z; acc.w -= v.w;
        }
        cnt = win > 0 ? win : 1;
    }

    const float inv = 1.0f / (float)cnt;
    outRow[tid] = make_float4(acc.x * inv, acc.y * inv, acc.z * inv, acc.w * inv);
    if (Mout != nullptr && tid == 0)
        Mout[(size_t)b * maxS + s] = 1.f;
}

extern "C" void kernel_launch(void* const* d_in, const int* in_sizes, int n_in,
                              void* d_out, int out_size)
{
    const float* H    = (const float*)d_in[0];
    const float* lens = (const float*)d_in[1];
    float* out        = (float*)d_out;

    const int B = in_sizes[1];  // 32

    // Infer maxS and mask presence from out_size (768, 769 coprime; maxS << 768).
    int maxS;
    bool has_mask;
    if (out_size % (B * (D_DIM + 1)) == 0) {
        maxS = out_size / (B * (D_DIM + 1));
        has_mask = true;
    } else {
        maxS = out_size / (B * D_DIM);
        has_mask = false;
    }

    float* Mout = has_mask ? (out + (size_t)B * maxS * D_DIM) : nullptr;

    dim3 grid1(MAX_NHOP, MAX_NP, B);
    piece_sum_kernel<<<grid1, NTHREADS>>>(H, lens);

    dim3 grid2(maxS, B);
    seg_out_kernel<<<grid2, NTHREADS>>>(H, out, Mout, maxS);
}

// round 11
// speedup vs baseline: 1.0621x; 1.0621x over previous
#include <cuda_runtime.h>
#include <cuda_bf16.h>

// SegmentalEmotion: per-sample sliding-window segment means (3-kernel).
// H: [B, T, D] fp32, lengths_sec: [B] fp32.
// Output: S_pad [B, maxS, D] fp32 (+ mask [B, maxS] fp32 appended, auto-detect).
//
// Reference plan (numpy fp64):
//   dur = max(len, 0.001); fps = T/dur
//   win = max(1, rint(fps)); hop = max(1, rint(fps*0.5))
//   n = (T >= win) ? (T-win)/hop + 1 : 0 ; n==0 -> fallback full-T mean
//
// Ledger (R3-R10): workers MUST read the plan from a pre-built table; every
// in-worker plan recompute variant (fp64/int x thread0/warp/per-thread/flag-
// spin) cost +4..7us by disrupting the front-batched LDG stream. The plan
// node itself measured ~5.1us at grid=1 regardless of content -> low-grid
// single-CTA pathology (B300 pSmIssueThrottle vanishes @grid>=148). So the
// plan kernel now launches 148 redundant blocks (all compute, block 0
// writes) to escape the low-grid regime.
//
// Integer-exact rint(1500/len) (no fp64 pipe for len in [1,1024)):
//   len = m * 2^(e-24)  (frexpf; m 24-bit int, exact)
//   rint decided by  3000*2^(24-e) <=> (2k+/-1)*m  (int64, exact),
//   round-half-to-even on ties; fp32 divide seeds candidate k.
//
// Phase 1 (piece_sum): 3D grid (60,4,B); hop-chunks split into <=4 pieces of
//   ~19-38 frames; reads H exactly once, streaming loads. (R3 champion shape.)
// Phase 2 (seg_out): window s = pieces of chunks s, s+1 (+/- <=1 edge frame),
//   scale 1/win, write output + mask.

#define T_FRAMES 1500
#define D_DIM    768
#define D_VEC    (D_DIM / 4)   // 192 float4 lanes
#define NTHREADS 192
#define MAX_B    32
#define MAX_NHOP 60            // ceil(1500/25)
#define MAX_NP   4
#define PIECE_TGT 38           // target frames per piece
#define PLAN_GRID 148          // >= SM count: escape low-grid throttle

// piece sums: P[b, j, p, :]
__device__ float g_P[(size_t)MAX_B * MAX_NHOP * MAX_NP * D_DIM];
// plan[b]: {win, hop, n_eff, nhop | np, plen, fallback, pad}  (2 x int4)
__device__ __align__(16) int g_plan[MAX_B][8];

// rint(num/len) via exact int64 comparisons. lhs = 2*num * 2^(24-e),
// m = 24-bit mantissa of len, k = fp32 candidate (within +-1 of truth).
__device__ __forceinline__ int rint_ratio_exact(long long lhs, long long m, int k)
{
    while (lhs > (2LL * k + 1) * m) ++k;   // x > k+0.5
    while (lhs < (2LL * k - 1) * m) --k;   // x < k-0.5
    if (lhs == (2LL * k + 1) * m) return k + (k & 1);  // tie at k+0.5 -> even
    if (lhs == (2LL * k - 1) * m) return k - (k & 1);  // tie at k-0.5 -> even
    return k;
}

// ---------- Phase 0: plan kernel, 148 redundant blocks (block 0 writes) ----------
__global__ void plan_kernel(const float* __restrict__ lens, int B)
{
    int b = threadIdx.x;
    if (b >= B) return;
    float len = __ldg(&lens[b]);

    int win, hop;
    long long n;
    if (len >= 1.0f && len < 1024.0f) {
        int e;
        float mf = frexpf(len, &e);                    // len = mf*2^e
        long long m = (long long)(mf * 16777216.0f);   // mf*2^24, exact
        const int sh = 24 - e;                         // in [14, 23]
        win = rint_ratio_exact(3000LL << sh, m, (int)lrintf(1500.0f / len));
        hop = rint_ratio_exact(1500LL << sh, m, (int)lrintf(750.0f / len));
        if (win < 1) win = 1;
        if (hop < 1) hop = 1;
        n = (T_FRAMES >= win) ? (long long)(T_FRAMES - win) / hop + 1 : 0;
    } else {
        // exact fp64 replica (never taken for len in [5,30))
        double dur = fmax((double)len, 0.001);
        double fps = (double)T_FRAMES / dur;
        long long w64 = llrint(fps);       if (w64 < 1) w64 = 1;
        long long h64 = llrint(fps * 0.5); if (h64 < 1) h64 = 1;
        n = ((long long)T_FRAMES >= w64)
                ? ((long long)T_FRAMES - w64) / h64 + 1 : 0;
        if (w64 > T_FRAMES + 1) w64 = T_FRAMES + 1;
        if (h64 > T_FRAMES) h64 = T_FRAMES;
        win = (int)w64;
        hop = (int)h64;
    }

    int fallback = (n == 0);
    int nhop = (T_FRAMES + hop - 1) / hop;
    int np = (hop + PIECE_TGT - 1) / PIECE_TGT;
    if (np > MAX_NP) np = MAX_NP;
    int plen = (hop + np - 1) / np;

    if (blockIdx.x == 0) {
        int4 lo = make_int4(win, hop, (int)(fallback ? 1 : n), nhop);
        int4 hi = make_int4(np, plen, fallback, 0);
        *(int4*)&g_plan[b][0] = lo;
        *(int4*)&g_plan[b][4] = hi;
    }
}

// ---------- Phase 1: piece sums, reads H exactly once (R3 shape) ----------
__global__ __launch_bounds__(NTHREADS)
void piece_sum_kernel(const float* __restrict__ H)
{
    const int j   = blockIdx.x;   // hop-chunk index
    const int p   = blockIdx.y;   // piece within chunk
    const int b   = blockIdx.z;
    const int tid = threadIdx.x;

    const int4 plo = __ldg((const int4*)&g_plan[b][0]);  // win,hop,n_eff,nhop
    const int4 phi = __ldg((const int4*)&g_plan[b][4]);  // np,plen,fallback
    const int hop  = plo.y;
    const int nhop = plo.w;
    const int np   = phi.x;
    const int plen = phi.y;
    if (j >= nhop || p >= np) return;

    int t0 = j * hop + p * plen;
    int chunk_end = j * hop + hop;
    if (chunk_end > T_FRAMES) chunk_end = T_FRAMES;
    int t1 = t0 + plen;
    if (t1 > chunk_end) t1 = chunk_end;

    const float4* __restrict__ Hb =
        (const float4*)H + (size_t)b * T_FRAMES * D_VEC + tid;

    float4 acc = make_float4(0.f, 0.f, 0.f, 0.f);
    int t = t0;
    for (; t + 8 <= t1; t += 8) {
        float4 v0 = __ldcs(&Hb[(t + 0) * D_VEC]);
        float4 v1 = __ldcs(&Hb[(t + 1) * D_VEC]);
        float4 v2 = __ldcs(&Hb[(t + 2) * D_VEC]);
        float4 v3 = __ldcs(&Hb[(t + 3) * D_VEC]);
        float4 v4 = __ldcs(&Hb[(t + 4) * D_VEC]);
        float4 v5 = __ldcs(&Hb[(t + 5) * D_VEC]);
        float4 v6 = __ldcs(&Hb[(t + 6) * D_VEC]);
        float4 v7 = __ldcs(&Hb[(t + 7) * D_VEC]);
        acc.x += v0.x + v1.x + v2.x + v3.x + v4.x + v5.x + v6.x + v7.x;
        acc.y += v0.y + v1.y + v2.y + v3.y + v4.y + v5.y + v6.y + v7.y;
        acc.z += v0.z + v1.z + v2.z + v3.z + v4.z + v5.z + v6.z + v7.z;
        acc.w += v0.w + v1.w + v2.w + v3.w + v4.w + v5.w + v6.w + v7.w;
    }
    for (; t < t1; ++t) {
        float4 v = __ldcs(&Hb[t * D_VEC]);
        acc.x += v.x; acc.y += v.y; acc.z += v.z; acc.w += v.w;
    }

    ((float4*)g_P)[(((size_t)b * MAX_NHOP + j) * MAX_NP + p) * D_VEC + tid] = acc;
}

// ---------- Phase 2: combine piece sums + edge correction ----------
__global__ __launch_bounds__(NTHREADS)
void seg_out_kernel(const float* __restrict__ H,
                    float* __restrict__ S,      // [B, maxS, D]
                    float* __restrict__ Mout,   // [B, maxS] or nullptr
                    int maxS)
{
    const int s   = blockIdx.x;
    const int b   = blockIdx.y;
    const int tid = threadIdx.x;

    const int4 plo = __ldg((const int4*)&g_plan[b][0]);  // win,hop,n_eff,nhop
    const int4 phi = __ldg((const int4*)&g_plan[b][4]);  // np,plen,fallback
    const int win      = plo.x;
    const int hop      = plo.y;
    const int n_eff    = plo.z;
    const int nhop     = plo.w;
    const int np       = phi.x;
    const int fallback = phi.z;

    float4* outRow = (float4*)(S + ((size_t)b * maxS + s) * D_DIM);

    if (s >= n_eff) {
        outRow[tid] = make_float4(0.f, 0.f, 0.f, 0.f);
        if (Mout != nullptr && tid == 0)
            Mout[(size_t)b * maxS + s] = 0.f;
        return;
    }

    const float4* __restrict__ Pb =
        (const float4*)g_P + (size_t)b * MAX_NHOP * MAX_NP * D_VEC + tid;
    const float4* __restrict__ Hb =
        (const float4*)H + (size_t)b * T_FRAMES * D_VEC + tid;

    float4 acc = make_float4(0.f, 0.f, 0.f, 0.f);
    int cnt;

    if (fallback) {
        for (int j = 0; j < nhop; ++j)
            for (int p = 0; p < np; ++p) {
                float4 v = Pb[((size_t)j * MAX_NP + p) * D_VEC];
                acc.x += v.x; acc.y += v.y; acc.z += v.z; acc.w += v.w;
            }
        cnt = T_FRAMES;
    } else {
        const int start = s * hop;
        const int end   = start + win;           // <= T by definition of n
        const bool have2 = (s + 1) < nhop;

        #pragma unroll
        for (int p = 0; p < MAX_NP; ++p) {
            if (p < np) {
                float4 v = Pb[((size_t)s * MAX_NP + p) * D_VEC];
                acc.x += v.x; acc.y += v.y; acc.z += v.z; acc.w += v.w;
            }
        }
        if (have2) {
            #pragma unroll
            for (int p = 0; p < MAX_NP; ++p) {
                if (p < np) {
                    float4 v = Pb[((size_t)(s + 1) * MAX_NP + p) * D_VEC];
                    acc.x += v.x; acc.y += v.y; acc.z += v.z; acc.w += v.w;
                }
            }
        }
        // chunks s (+ s+1) cover [start, cov_end)
        int cov_end = start + (have2 ? 2 : 1) * hop;
        if (cov_end > T_FRAMES) cov_end = T_FRAMES;

        for (int t = cov_end; t < end; ++t) {     // add missing (<=1)
            float4 v = Hb[t * D_VEC];
            acc.x += v.x; acc.y += v.y; acc.z += v.z; acc.w += v.w;
        }
        for (int t = end; t < cov_end; ++t) {     // subtract excess (<=1)
            float4 v = Hb[t * D_VEC];
            acc.x -= v.x; acc.y -= v.y; acc.z -= v.z; acc.w -= v.w;
        }
        cnt = win > 0 ? win : 1;
    }

    const float inv = 1.0f / (float)cnt;
    outRow[tid] = make_float4(acc.x * inv, acc.y * inv, acc.z * inv, acc.w * inv);
    if (Mout != nullptr && tid == 0)
        Mout[(size_t)b * maxS + s] = 1.f;
}

extern "C" void kernel_launch(void* const* d_in, const int* in_sizes, int n_in,
                              void* d_out, int out_size)
{
    const float* H    = (const float*)d_in[0];
    const float* lens = (const float*)d_in[1];
    float* out        = (float*)d_out;

    const int B = in_sizes[1];  // 32

    // Infer maxS and mask presence from out_size (768, 769 coprime; maxS << 768).
    int maxS;
    bool has_mask;
    if (out_size % (B * (D_DIM + 1)) == 0) {
        maxS = out_size / (B * (D_DIM + 1));
        has_mask = true;
    } else {
        maxS = out_size / (B * D_DIM);
        has_mask = false;
    }

    float* Mout = has_mask ? (out + (size_t)B * maxS * D_DIM) : nullptr;

    plan_kernel<<<PLAN_GRID, 32>>>(lens, B);

    dim3 grid1(MAX_NHOP, MAX_NP, B);
    piece_sum_kernel<<<grid1, NTHREADS>>>(H);

    dim3 grid2(maxS, B);
    seg_out_kernel<<<grid2, NTHREADS>>>(H, out, Mout, maxS);
}